// round 9
// baseline (speedup 1.0000x reference)
#include <cuda_runtime.h>

// SpikingLayer: input (B*T, 32*32*32) f32, B=16, T=128.
// Per (b, feat): state = max(syn_t + state - act, -1); act = s>0 ? floor(s) : 0.
//
// Pure HBM stream: 268MB in + 268MB out, DRAM-turnaround bound (~6.1 TB/s
// plateau across 7 variants). R8 probe: float2 per thread instead of float4
// -> 262144 threads (2048 CTAs x 128) -> ~86% occupancy vs 41%. Doubles the
// number of independent memory requesters per SM (finer request interleave
// at the MC, 256B/warp transactions) while staying far below the LSU issue
// floor. 4-deep software pipeline retained (8 LDG.64 in flight per thread).

#define T_STEPS 128
#define FEAT    32768            // 32*32*32
#define F2      (FEAT / 2)       // 16384 float2 per time step
#define BATCH   16

__global__ __launch_bounds__(128, 16)
void spiking_layer_kernel(const float2* __restrict__ x, float2* __restrict__ out) {
    const unsigned tid = blockIdx.x * blockDim.x + threadIdx.x;  // 0 .. 262143
    const unsigned b = tid >> 14;        // / 16384
    const unsigned f = tid & (F2 - 1);   // % 16384

    const size_t base = (size_t)b * T_STEPS * F2 + f;
    const float2* __restrict__ in = x + base;
    float2* __restrict__ o = out + base;

    float sx = 0.f, sy = 0.f;   // membrane state
    float ax = 0.f, ay = 0.f;   // last activation

    #define STEP_STORE(v, t_idx)                                          \
        sx = fmaxf(v.x + sx - ax, -1.0f);                                 \
        sy = fmaxf(v.y + sy - ay, -1.0f);                                 \
        ax = (sx > 0.f) ? floorf(sx) : 0.f;                               \
        ay = (sy > 0.f) ? floorf(sy) : 0.f;                               \
        __stcs(o + (size_t)(t_idx) * F2, make_float2(ax, ay));

    // Prologue: load chunk 0 (t = 0..3)
    float2 c0 = __ldcs(in + 0 * (size_t)F2);
    float2 c1 = __ldcs(in + 1 * (size_t)F2);
    float2 c2 = __ldcs(in + 2 * (size_t)F2);
    float2 c3 = __ldcs(in + 3 * (size_t)F2);

    #pragma unroll 1
    for (int t = 0; t < T_STEPS - 4; t += 4) {
        // Prefetch next chunk first (keeps 8 LDG.64 in flight per thread)
        float2 n0 = __ldcs(in + (size_t)(t + 4) * F2);
        float2 n1 = __ldcs(in + (size_t)(t + 5) * F2);
        float2 n2 = __ldcs(in + (size_t)(t + 6) * F2);
        float2 n3 = __ldcs(in + (size_t)(t + 7) * F2);

        STEP_STORE(c0, t + 0);
        STEP_STORE(c1, t + 1);
        STEP_STORE(c2, t + 2);
        STEP_STORE(c3, t + 3);

        c0 = n0; c1 = n1; c2 = n2; c3 = n3;
    }

    // Epilogue: t = 124..127
    STEP_STORE(c0, T_STEPS - 4);
    STEP_STORE(c1, T_STEPS - 3);
    STEP_STORE(c2, T_STEPS - 2);
    STEP_STORE(c3, T_STEPS - 1);

    #undef STEP_STORE
}

extern "C" void kernel_launch(void* const* d_in, const int* in_sizes, int n_in,
                              void* d_out, int out_size) {
    const float2* x = (const float2*)d_in[0];
    float2* o = (float2*)d_out;
    const int total_threads = BATCH * F2;          // 262144
    spiking_layer_kernel<<<total_threads / 128, 128>>>(x, o);
}

// round 10
// speedup vs baseline: 1.0459x; 1.0459x over previous
#include <cuda_runtime.h>

// SpikingLayer: input (B*T, 32*32*32) f32, B=16, T=128.
// Per (b, feat): state = max(syn_t + state - act, -1); act = s>0 ? floor(s) : 0.
//
// Pure HBM stream: 268MB in + 268MB out, DRAM-bound plateau ~6.1 TB/s across
// 8 variants (CTA shape, pipe depth, store batching, occupancy 41% vs 81% all
// neutral). R9 probe: write-THROUGH stores (__stwt) instead of streaming
// write-back (__stcs) - output is never re-read, so skipping dirty-line
// residency removes lazy-writeback interleave against demand reads at the
// DRAM banks. Base config = measured argmin (1024 CTAs x 128 thr, 4-deep
// software-pipelined prefetch, 8 LDG.128 in flight per thread).

#define T_STEPS 128
#define FEAT    32768            // 32*32*32
#define F4      (FEAT / 4)       // 8192 float4 per time step
#define BATCH   16

__global__ __launch_bounds__(128, 8)
void spiking_layer_kernel(const float4* __restrict__ x, float4* __restrict__ out) {
    const unsigned tid = blockIdx.x * blockDim.x + threadIdx.x;  // 0 .. 131071
    const unsigned b = tid >> 13;        // / 8192
    const unsigned f = tid & (F4 - 1);   // % 8192

    const size_t base = (size_t)b * T_STEPS * F4 + f;
    const float4* __restrict__ in = x + base;
    float4* __restrict__ o = out + base;

    float sx = 0.f, sy = 0.f, sz = 0.f, sw = 0.f;   // membrane state
    float ax = 0.f, ay = 0.f, az = 0.f, aw = 0.f;   // last activation

    #define STEP_STORE(v, t_idx)                                          \
        sx = fmaxf(v.x + sx - ax, -1.0f);                                 \
        sy = fmaxf(v.y + sy - ay, -1.0f);                                 \
        sz = fmaxf(v.z + sz - az, -1.0f);                                 \
        sw = fmaxf(v.w + sw - aw, -1.0f);                                 \
        ax = (sx > 0.f) ? floorf(sx) : 0.f;                               \
        ay = (sy > 0.f) ? floorf(sy) : 0.f;                               \
        az = (sz > 0.f) ? floorf(sz) : 0.f;                               \
        aw = (sw > 0.f) ? floorf(sw) : 0.f;                               \
        __stwt(o + (size_t)(t_idx) * F4, make_float4(ax, ay, az, aw));

    // Prologue: load chunk 0 (t = 0..3)
    float4 c0 = __ldcs(in + 0 * (size_t)F4);
    float4 c1 = __ldcs(in + 1 * (size_t)F4);
    float4 c2 = __ldcs(in + 2 * (size_t)F4);
    float4 c3 = __ldcs(in + 3 * (size_t)F4);

    #pragma unroll 1
    for (int t = 0; t < T_STEPS - 4; t += 4) {
        // Prefetch next chunk before touching current one (keeps 8 loads in flight)
        float4 n0 = __ldcs(in + (size_t)(t + 4) * F4);
        float4 n1 = __ldcs(in + (size_t)(t + 5) * F4);
        float4 n2 = __ldcs(in + (size_t)(t + 6) * F4);
        float4 n3 = __ldcs(in + (size_t)(t + 7) * F4);

        STEP_STORE(c0, t + 0);
        STEP_STORE(c1, t + 1);
        STEP_STORE(c2, t + 2);
        STEP_STORE(c3, t + 3);

        c0 = n0; c1 = n1; c2 = n2; c3 = n3;
    }

    // Epilogue: t = 124..127
    STEP_STORE(c0, T_STEPS - 4);
    STEP_STORE(c1, T_STEPS - 3);
    STEP_STORE(c2, T_STEPS - 2);
    STEP_STORE(c3, T_STEPS - 1);

    #undef STEP_STORE
}

extern "C" void kernel_launch(void* const* d_in, const int* in_sizes, int n_in,
                              void* d_out, int out_size) {
    const float4* x = (const float4*)d_in[0];
    float4* o = (float4*)d_out;
    const int total_threads = BATCH * F4;          // 131072
    spiking_layer_kernel<<<total_threads / 128, 128>>>(x, o);
}